// round 3
// baseline (speedup 1.0000x reference)
#include <cuda_runtime.h>

// ---------------------------------------------------------------------------
// searchMaskCrossAttention: fused QKV projection + flash cross-attention with
// additive position bias + output projection.  All fp32.
//   B=16, Lq=1024, Lkv=1424, DIM=384, HEADS=8, HEAD_DIM=48, TEM_LEN=400
// ---------------------------------------------------------------------------

constexpr int B    = 16;
constexpr int H    = 8;
constexpr int DIM  = 384;
constexpr int HD   = 48;
constexpr int LQ   = 1024;
constexpr int LKV  = 1424;
constexpr int TEM  = 400;
constexpr float ATTN_SCALE = 0.14433756729740643f;  // 48^-0.5

// Scratch (device globals: allocation-free under harness rules)
__device__ float g_qh[B * H * LQ * HD];    // (b,h,q,d)   25 MB
__device__ float g_kh[B * H * LKV * HD];   // (b,h,s,d)   35 MB
__device__ float g_vh[B * H * LKV * HD];   // (b,h,s,d)   35 MB
__device__ float g_x [B * LQ * DIM];       // (b,q,h*48+d) 25 MB

// ---------------------------------------------------------------------------
// SGEMM: out[m][n] = sum_k A[m][k] * W[n][k] + bias[n], K = 384 fixed.
// Block tile 128x128, BK=16, 256 threads, 8x8 microtile.
// MODE 0: q-projection  -> scatter to g_qh
// MODE 1: kv-projection -> split k/v, add masks, scatter to g_kh/g_vh
// MODE 2: out-projection-> reads g_x, writes d_out
// ---------------------------------------------------------------------------
template <int MODE>
__global__ __launch_bounds__(256) void sgemm_kernel(
    const float* __restrict__ A, const float* __restrict__ W,
    const float* __restrict__ bias,
    const float* __restrict__ tmask, const float* __restrict__ smask,
    float* __restrict__ out)
{
    __shared__ __align__(16) float As[16][128];
    __shared__ __align__(16) float Bs[16][128];

    const int m0  = blockIdx.y * 128;
    const int n0  = blockIdx.x * 128;
    const int tid = threadIdx.x;
    const int tx  = tid & 15;
    const int ty  = tid >> 4;

    float acc[8][8];
#pragma unroll
    for (int i = 0; i < 8; i++)
#pragma unroll
        for (int j = 0; j < 8; j++) acc[i][j] = 0.0f;

    const float* Aptr = (MODE == 2) ? (&g_x[0] + (size_t)m0 * DIM)
                                    : (A + (size_t)m0 * DIM);
    const float* Wptr = W + (size_t)n0 * DIM;

    for (int k0 = 0; k0 < DIM; k0 += 16) {
#pragma unroll
        for (int l = 0; l < 2; l++) {
            int idx = tid + 256 * l;
            int row = idx >> 2;            // 0..127
            int c4  = (idx & 3) << 2;      // 0,4,8,12
            float4 a = *(const float4*)(Aptr + (size_t)row * DIM + k0 + c4);
            As[c4 + 0][row] = a.x; As[c4 + 1][row] = a.y;
            As[c4 + 2][row] = a.z; As[c4 + 3][row] = a.w;
            float4 b = *(const float4*)(Wptr + (size_t)row * DIM + k0 + c4);
            Bs[c4 + 0][row] = b.x; Bs[c4 + 1][row] = b.y;
            Bs[c4 + 2][row] = b.z; Bs[c4 + 3][row] = b.w;
        }
        __syncthreads();
#pragma unroll
        for (int kk = 0; kk < 16; kk++) {
            float af[8], bf[8];
            *(float4*)&af[0] = *(const float4*)&As[kk][ty * 8];
            *(float4*)&af[4] = *(const float4*)&As[kk][ty * 8 + 4];
            *(float4*)&bf[0] = *(const float4*)&Bs[kk][tx * 8];
            *(float4*)&bf[4] = *(const float4*)&Bs[kk][tx * 8 + 4];
#pragma unroll
            for (int i = 0; i < 8; i++)
#pragma unroll
                for (int j = 0; j < 8; j++)
                    acc[i][j] += af[i] * bf[j];
        }
        __syncthreads();
    }

    // Epilogue
#pragma unroll
    for (int i = 0; i < 8; i++) {
        int m = m0 + ty * 8 + i;
#pragma unroll
        for (int j = 0; j < 8; j++) {
            int n = n0 + tx * 8 + j;
            float v = acc[i][j] + bias[n];
            if (MODE == 0) {
                int b  = m >> 10;
                int qi = m & 1023;
                int h  = n / HD;
                int d  = n - h * HD;
                g_qh[((b * H + h) * LQ + qi) * HD + d] = v;
            } else if (MODE == 1) {
                int b = m / LKV;
                int s = m - b * LKV;
                if (n < DIM) {
                    int h = n / HD, d = n - h * HD;
                    g_kh[((b * H + h) * LKV + s) * HD + d] = v;
                } else {
                    int nv = n - DIM;
                    float mv = (s < TEM)
                        ? tmask[((size_t)(b * TEM + s)) * DIM + nv]
                        : smask[((size_t)(b * (LKV - TEM) + (s - TEM))) * DIM + nv];
                    v += mv;
                    int h = nv / HD, d = nv - h * HD;
                    g_vh[((b * H + h) * LKV + s) * HD + d] = v;
                }
            } else {
                out[(size_t)m * DIM + n] = v;
            }
        }
    }
}

// ---------------------------------------------------------------------------
// Flash attention with additive bias.
// Block: one (b, h, q-tile of 64).  256 threads = 16x16.
// S-phase microtile 4x4 (rows ty*4.., cols tx*4..), PV-phase 4x3 (cols tx*3..).
// K and V share one smem buffer, both stored transposed [d][kv]; V is carried
// in registers across the S phase.  All smem fragment reads are float4,
// conflict-free.
// ---------------------------------------------------------------------------
__global__ __launch_bounds__(256, 2) void attn_kernel(const float* __restrict__ pos)
{
    __shared__ __align__(16) float Qs [64][52];  // [q][d]
    __shared__ __align__(16) float KVT[48][68];  // [d][kv]  (K, then V)
    __shared__ __align__(16) float Ps [64][68];  // [q][kv]

    const int bid = blockIdx.x;
    const int b   = bid & 15;          // batch fastest -> attn_pos reuse in L2
    const int qt  = (bid >> 4) & 15;
    const int h   = bid >> 8;
    const int tid = threadIdx.x;
    const int tx  = tid & 15;
    const int ty  = tid >> 4;
    const int q0  = qt * 64;

    // Load Q tile (64 x 48)
    const float* qbase = g_qh + ((size_t)((b * H + h) * LQ + q0)) * HD;
#pragma unroll
    for (int l = 0; l < 3; l++) {
        int i  = tid + 256 * l;
        int r  = i / 12;
        int c4 = (i % 12) * 4;
        *(float4*)&Qs[r][c4] = *(const float4*)(qbase + (size_t)r * HD + c4);
    }

    const float* kbase = g_kh + ((size_t)((b * H + h)) * LKV) * HD;
    const float* vbase = g_vh + ((size_t)((b * H + h)) * LKV) * HD;
    const float* pbase = pos + ((size_t)h * LQ + q0) * (size_t)LKV;

    float m_r[4], l_r[4], O[4][3];
#pragma unroll
    for (int r = 0; r < 4; r++) {
        m_r[r] = -1e30f;
        l_r[r] = 0.0f;
#pragma unroll
        for (int c = 0; c < 3; c++) O[r][c] = 0.0f;
    }

    constexpr int NT = (LKV + 63) / 64;  // 23 (last tile has 16 valid rows)

    for (int t = 0; t < NT; t++) {
        const int kv0 = t * 64;

        // Issue global K/V loads into registers (overlaps with sync/compute)
        float4 kf4[3], vf4[3];
        int rr[3], cc[3];
#pragma unroll
        for (int l = 0; l < 3; l++) {
            int i  = tid + 256 * l;
            int r  = i / 12;
            int c4 = (i % 12) * 4;
            rr[l] = r; cc[l] = c4;
            int row = kv0 + r;
            if (row < LKV) {
                kf4[l] = *(const float4*)(kbase + (size_t)row * HD + c4);
                vf4[l] = *(const float4*)(vbase + (size_t)row * HD + c4);
            } else {
                kf4[l] = make_float4(0.f, 0.f, 0.f, 0.f);
                vf4[l] = make_float4(0.f, 0.f, 0.f, 0.f);
            }
        }
        __syncthreads();  // previous tile's P@V (and Q load on t=0) complete

        // Store K transposed: KVT[d][kv]
#pragma unroll
        for (int l = 0; l < 3; l++) {
            KVT[cc[l] + 0][rr[l]] = kf4[l].x;
            KVT[cc[l] + 1][rr[l]] = kf4[l].y;
            KVT[cc[l] + 2][rr[l]] = kf4[l].z;
            KVT[cc[l] + 3][rr[l]] = kf4[l].w;
        }
        __syncthreads();

        // ---- S = Q @ K^T  (4x4 per thread) ----
        float s[4][4];
#pragma unroll
        for (int r = 0; r < 4; r++)
#pragma unroll
            for (int c = 0; c < 4; c++) s[r][c] = 0.0f;

#pragma unroll
        for (int d4 = 0; d4 < 12; d4++) {
            float qv[4][4], kv_[4][4];
#pragma unroll
            for (int r = 0; r < 4; r++)
                *(float4*)qv[r] = *(const float4*)&Qs[ty * 4 + r][d4 * 4];
#pragma unroll
            for (int j = 0; j < 4; j++)
                *(float4*)kv_[j] = *(const float4*)&KVT[d4 * 4 + j][tx * 4];
#pragma unroll
            for (int r = 0; r < 4; r++)
#pragma unroll
                for (int c = 0; c < 4; c++)
                    s[r][c] += qv[r][0] * kv_[0][c] + qv[r][1] * kv_[1][c]
                             + qv[r][2] * kv_[2][c] + qv[r][3] * kv_[3][c];
        }

        // ---- bias + scale + mask + online softmax ----
        const int kvloc = tx * 4;
#pragma unroll
        for (int r = 0; r < 4; r++) {
            float pv[4];
            const float* pp = pbase + (size_t)(ty * 4 + r) * LKV + kv0 + kvloc;
            if (kv0 + kvloc + 3 < LKV) {
                *(float4*)pv = *(const float4*)pp;
            } else {
#pragma unroll
                for (int c = 0; c < 4; c++)
                    pv[c] = (kv0 + kvloc + c < LKV) ? pp[c] : 0.0f;
            }
#pragma unroll
            for (int c = 0; c < 4; c++) {
                bool valid = (kv0 + kvloc + c) < LKV;
                s[r][c] = valid ? (s[r][c] * ATTN_SCALE + pv[c]) : -1e30f;
            }
            float mt = fmaxf(fmaxf(s[r][0], s[r][1]), fmaxf(s[r][2], s[r][3]));
#pragma unroll
            for (int off = 1; off < 16; off <<= 1)
                mt = fmaxf(mt, __shfl_xor_sync(0xffffffffu, mt, off));
            float mnew  = fmaxf(m_r[r], mt);
            float alpha = __expf(m_r[r] - mnew);
            m_r[r] = mnew;
            float rs = 0.0f;
#pragma unroll
            for (int c = 0; c < 4; c++) {
                float p = __expf(s[r][c] - mnew);
                s[r][c] = p;
                rs += p;
            }
#pragma unroll
            for (int off = 1; off < 16; off <<= 1)
                rs += __shfl_xor_sync(0xffffffffu, rs, off);
            l_r[r] = l_r[r] * alpha + rs;
#pragma unroll
            for (int c = 0; c < 3; c++) O[r][c] *= alpha;
            *(float4*)&Ps[ty * 4 + r][tx * 4] =
                make_float4(s[r][0], s[r][1], s[r][2], s[r][3]);
        }
        __syncthreads();  // Ps visible; K reads done -> KVT reusable

        // Store V transposed: KVT[d][kv]
#pragma unroll
        for (int l = 0; l < 3; l++) {
            KVT[cc[l] + 0][rr[l]] = vf4[l].x;
            KVT[cc[l] + 1][rr[l]] = vf4[l].y;
            KVT[cc[l] + 2][rr[l]] = vf4[l].z;
            KVT[cc[l] + 3][rr[l]] = vf4[l].w;
        }
        __syncthreads();

        // ---- O += P @ V  (4x3 per thread) ----
#pragma unroll
        for (int k4 = 0; k4 < 16; k4++) {
            float pf[4][4], vv[3][4];
#pragma unroll
            for (int r = 0; r < 4; r++)
                *(float4*)pf[r] = *(const float4*)&Ps[ty * 4 + r][k4 * 4];
#pragma unroll
            for (int c = 0; c < 3; c++)
                *(float4*)vv[c] = *(const float4*)&KVT[tx * 3 + c][k4 * 4];
#pragma unroll
            for (int r = 0; r < 4; r++)
#pragma unroll
                for (int c = 0; c < 3; c++)
                    O[r][c] += pf[r][0] * vv[c][0] + pf[r][1] * vv[c][1]
                             + pf[r][2] * vv[c][2] + pf[r][3] * vv[c][3];
        }
    }

    // ---- normalize + write x (b, q, h*48+d) ----
#pragma unroll
    for (int r = 0; r < 4; r++) {
        float inv = 1.0f / l_r[r];
        int qrow  = q0 + ty * 4 + r;
        float* xp = g_x + ((size_t)(b * LQ + qrow)) * DIM + h * HD + tx * 3;
#pragma unroll
        for (int c = 0; c < 3; c++) xp[c] = O[r][c] * inv;
    }
}

// ---------------------------------------------------------------------------
// Launch
// ---------------------------------------------------------------------------
extern "C" void kernel_launch(void* const* d_in, const int* in_sizes, int n_in,
                              void* d_out, int out_size)
{
    const float* tem_mask    = (const float*)d_in[0];
    const float* search_mask = (const float*)d_in[1];
    const float* q           = (const float*)d_in[2];
    const float* kv          = (const float*)d_in[3];
    const float* attn_pos    = (const float*)d_in[4];
    const float* q_w         = (const float*)d_in[5];
    const float* q_b         = (const float*)d_in[6];
    const float* kv_w        = (const float*)d_in[7];
    const float* kv_b        = (const float*)d_in[8];
    const float* proj_w      = (const float*)d_in[9];
    const float* proj_b      = (const float*)d_in[10];
    float* out = (float*)d_out;

    // q projection: (16*1024, 384) @ (384, 384)^T   -> g_qh
    sgemm_kernel<0><<<dim3(3, 128), 256>>>(q, q_w, q_b, nullptr, nullptr, nullptr);
    // kv projection: (16*1424, 384) @ (768, 384)^T  -> g_kh / g_vh (+masks)
    sgemm_kernel<1><<<dim3(6, 178), 256>>>(kv, kv_w, kv_b, tem_mask, search_mask, nullptr);
    // flash attention with bias                      -> g_x
    attn_kernel<<<B * H * (LQ / 64), 256>>>(attn_pos);
    // output projection: (16*1024, 384) @ (384,384)^T -> d_out
    sgemm_kernel<2><<<dim3(3, 128), 256>>>(nullptr, proj_w, proj_b, nullptr, nullptr, out);
}

// round 4
// speedup vs baseline: 1.0001x; 1.0001x over previous
#include <cuda_runtime.h>

// ---------------------------------------------------------------------------
// searchMaskCrossAttention: fused QKV projection + flash cross-attention with
// additive position bias + output projection.  All fp32 math, but the inner
// products use Blackwell packed fp32 (fma.rn.f32x2 -> SASS FFMA2) for 2x the
// scalar-FFMA issue rate.
//   B=16, Lq=1024, Lkv=1424, DIM=384, HEADS=8, HEAD_DIM=48, TEM_LEN=400
// ---------------------------------------------------------------------------

constexpr int B    = 16;
constexpr int H    = 8;
constexpr int DIM  = 384;
constexpr int HD   = 48;
constexpr int LQ   = 1024;
constexpr int LKV  = 1424;
constexpr int TEM  = 400;
constexpr float ATTN_SCALE = 0.14433756729740643f;  // 48^-0.5

using u64 = unsigned long long;

// ---- packed fp32 (f32x2) helpers: sm_100+ ---------------------------------
__device__ __forceinline__ u64 pk2(float lo, float hi) {
    u64 d; asm("mov.b64 %0, {%1, %2};" : "=l"(d) : "f"(lo), "f"(hi)); return d;
}
__device__ __forceinline__ u64 dup2(float x) { return pk2(x, x); }
__device__ __forceinline__ u64 fma2(u64 a, u64 b, u64 c) {
    u64 d; asm("fma.rn.f32x2 %0, %1, %2, %3;" : "=l"(d) : "l"(a), "l"(b), "l"(c));
    return d;
}
__device__ __forceinline__ u64 mul2(u64 a, u64 b) {
    u64 d; asm("mul.rn.f32x2 %0, %1, %2;" : "=l"(d) : "l"(a), "l"(b)); return d;
}
__device__ __forceinline__ float2 up2(u64 d) {
    float2 r; asm("mov.b64 {%0, %1}, %2;" : "=f"(r.x), "=f"(r.y) : "l"(d)); return r;
}

// Scratch (device globals: allocation-free under harness rules)
__device__ float g_qh[B * H * LQ * HD];    // (b,h,q,d)
__device__ float g_kh[B * H * LKV * HD];   // (b,h,s,d)
__device__ float g_vh[B * H * LKV * HD];   // (b,h,s,d)
__device__ float g_x [B * LQ * DIM];       // (b,q,h*48+d)

// ---------------------------------------------------------------------------
// SGEMM: out[m][n] = sum_k A[m][k] * W[n][k] + bias[n], K = 384 fixed.
// Block tile 128x128, BK=16, 256 threads, 8x8 microtile (f32x2: 8x4 pairs).
// ---------------------------------------------------------------------------
template <int MODE>
__global__ __launch_bounds__(256) void sgemm_kernel(
    const float* __restrict__ A, const float* __restrict__ W,
    const float* __restrict__ bias,
    const float* __restrict__ tmask, const float* __restrict__ smask,
    float* __restrict__ out)
{
    __shared__ __align__(16) float As[16][128];
    __shared__ __align__(16) float Bs[16][128];

    const int m0  = blockIdx.y * 128;
    const int n0  = blockIdx.x * 128;
    const int tid = threadIdx.x;
    const int tx  = tid & 15;
    const int ty  = tid >> 4;

    u64 acc2[8][4];
#pragma unroll
    for (int i = 0; i < 8; i++)
#pragma unroll
        for (int j = 0; j < 4; j++) acc2[i][j] = 0ull;

    const float* Aptr = (MODE == 2) ? (&g_x[0] + (size_t)m0 * DIM)
                                    : (A + (size_t)m0 * DIM);
    const float* Wptr = W + (size_t)n0 * DIM;

    for (int k0 = 0; k0 < DIM; k0 += 16) {
#pragma unroll
        for (int l = 0; l < 2; l++) {
            int idx = tid + 256 * l;
            int row = idx >> 2;            // 0..127
            int c4  = (idx & 3) << 2;      // 0,4,8,12
            float4 a = *(const float4*)(Aptr + (size_t)row * DIM + k0 + c4);
            As[c4 + 0][row] = a.x; As[c4 + 1][row] = a.y;
            As[c4 + 2][row] = a.z; As[c4 + 3][row] = a.w;
            float4 b = *(const float4*)(Wptr + (size_t)row * DIM + k0 + c4);
            Bs[c4 + 0][row] = b.x; Bs[c4 + 1][row] = b.y;
            Bs[c4 + 2][row] = b.z; Bs[c4 + 3][row] = b.w;
        }
        __syncthreads();
#pragma unroll
        for (int kk = 0; kk < 16; kk++) {
            float af[8];
            u64   bp[4];
            *(float4*)&af[0] = *(const float4*)&As[kk][ty * 8];
            *(float4*)&af[4] = *(const float4*)&As[kk][ty * 8 + 4];
            ulonglong2 b01 = *(const ulonglong2*)&Bs[kk][tx * 8];
            ulonglong2 b23 = *(const ulonglong2*)&Bs[kk][tx * 8 + 4];
            bp[0] = b01.x; bp[1] = b01.y; bp[2] = b23.x; bp[3] = b23.y;
#pragma unroll
            for (int i = 0; i < 8; i++) {
                u64 ad = dup2(af[i]);
#pragma unroll
                for (int j = 0; j < 4; j++)
                    acc2[i][j] = fma2(ad, bp[j], acc2[i][j]);
            }
        }
        __syncthreads();
    }

    // Epilogue
#pragma unroll
    for (int i = 0; i < 8; i++) {
        int m = m0 + ty * 8 + i;
        float acc[8];
#pragma unroll
        for (int j = 0; j < 4; j++) {
            float2 v = up2(acc2[i][j]);
            acc[2 * j] = v.x; acc[2 * j + 1] = v.y;
        }
#pragma unroll
        for (int j = 0; j < 8; j++) {
            int n = n0 + tx * 8 + j;
            float v = acc[j] + bias[n];
            if (MODE == 0) {
                int b  = m >> 10;
                int qi = m & 1023;
                int h  = n / HD;
                int d  = n - h * HD;
                g_qh[((b * H + h) * LQ + qi) * HD + d] = v;
            } else if (MODE == 1) {
                int b = m / LKV;
                int s = m - b * LKV;
                if (n < DIM) {
                    int h = n / HD, d = n - h * HD;
                    g_kh[((b * H + h) * LKV + s) * HD + d] = v;
                } else {
                    int nv = n - DIM;
                    float mv = (s < TEM)
                        ? tmask[((size_t)(b * TEM + s)) * DIM + nv]
                        : smask[((size_t)(b * (LKV - TEM) + (s - TEM))) * DIM + nv];
                    v += mv;
                    int h = nv / HD, d = nv - h * HD;
                    g_vh[((b * H + h) * LKV + s) * HD + d] = v;
                }
            } else {
                out[(size_t)m * DIM + n] = v;
            }
        }
    }
}

// ---------------------------------------------------------------------------
// Flash attention with additive bias.  Block: one (b, h, q-tile of 64),
// 256 threads = 16x16.  S-phase 4x4 per thread (f32x2 pairs over kv-cols),
// PV-phase 4x3 per thread (f32x2 pairs over q-rows).
// ---------------------------------------------------------------------------
__global__ __launch_bounds__(256, 2) void attn_kernel(const float* __restrict__ pos)
{
    __shared__ __align__(16) float Qs [64][52];  // [q][d]
    __shared__ __align__(16) float KVT[48][68];  // [d][kv]  (K, then V)
    __shared__ __align__(16) float Ps [64][68];  // [q][kv]

    const int bid = blockIdx.x;
    const int b   = bid & 15;          // batch fastest -> attn_pos reuse in L2
    const int qt  = (bid >> 4) & 15;
    const int h   = bid >> 8;
    const int tid = threadIdx.x;
    const int tx  = tid & 15;
    const int ty  = tid >> 4;
    const int q0  = qt * 64;

    // Load Q tile (64 x 48)
    const float* qbase = g_qh + ((size_t)((b * H + h) * LQ + q0)) * HD;
#pragma unroll
    for (int l = 0; l < 3; l++) {
        int i  = tid + 256 * l;
        int r  = i / 12;
        int c4 = (i % 12) * 4;
        *(float4*)&Qs[r][c4] = *(const float4*)(qbase + (size_t)r * HD + c4);
    }

    const float* kbase = g_kh + ((size_t)((b * H + h)) * LKV) * HD;
    const float* vbase = g_vh + ((size_t)((b * H + h)) * LKV) * HD;
    const float* pbase = pos + ((size_t)h * LQ + q0) * (size_t)LKV;

    float m_r[4], l_r[4];
    u64 O2[2][3];                       // [q-row pair][out col], rows (ty*4+2p, +2p+1)
#pragma unroll
    for (int r = 0; r < 4; r++) { m_r[r] = -1e30f; l_r[r] = 0.0f; }
#pragma unroll
    for (int p = 0; p < 2; p++)
#pragma unroll
        for (int c = 0; c < 3; c++) O2[p][c] = 0ull;

    constexpr int NT = (LKV + 63) / 64;  // 23 (last tile has 16 valid rows)

    for (int t = 0; t < NT; t++) {
        const int kv0 = t * 64;

        // Issue global K/V loads into registers (overlaps with sync/compute)
        float4 kf4[3], vf4[3];
        int rr[3], cc[3];
#pragma unroll
        for (int l = 0; l < 3; l++) {
            int i  = tid + 256 * l;
            int r  = i / 12;
            int c4 = (i % 12) * 4;
            rr[l] = r; cc[l] = c4;
            int row = kv0 + r;
            if (row < LKV) {
                kf4[l] = *(const float4*)(kbase + (size_t)row * HD + c4);
                vf4[l] = *(const float4*)(vbase + (size_t)row * HD + c4);
            } else {
                kf4[l] = make_float4(0.f, 0.f, 0.f, 0.f);
                vf4[l] = make_float4(0.f, 0.f, 0.f, 0.f);
            }
        }
        __syncthreads();  // previous tile's P@V (and Q load on t=0) complete

        // Store K transposed: KVT[d][kv]
#pragma unroll
        for (int l = 0; l < 3; l++) {
            KVT[cc[l] + 0][rr[l]] = kf4[l].x;
            KVT[cc[l] + 1][rr[l]] = kf4[l].y;
            KVT[cc[l] + 2][rr[l]] = kf4[l].z;
            KVT[cc[l] + 3][rr[l]] = kf4[l].w;
        }
        __syncthreads();

        // ---- S = Q @ K^T  (4 rows x 2 col-pairs per thread, FFMA2) ----
        u64 s2[4][2];
#pragma unroll
        for (int r = 0; r < 4; r++) { s2[r][0] = 0ull; s2[r][1] = 0ull; }

#pragma unroll
        for (int d4 = 0; d4 < 12; d4++) {
            float qv[4][4];
            u64   kp[4][2];
#pragma unroll
            for (int j = 0; j < 4; j++) {
                ulonglong2 kt = *(const ulonglong2*)&KVT[d4 * 4 + j][tx * 4];
                kp[j][0] = kt.x; kp[j][1] = kt.y;
            }
#pragma unroll
            for (int r = 0; r < 4; r++)
                *(float4*)qv[r] = *(const float4*)&Qs[ty * 4 + r][d4 * 4];
#pragma unroll
            for (int r = 0; r < 4; r++)
#pragma unroll
                for (int j = 0; j < 4; j++) {
                    u64 qd = dup2(qv[r][j]);
                    s2[r][0] = fma2(qd, kp[j][0], s2[r][0]);
                    s2[r][1] = fma2(qd, kp[j][1], s2[r][1]);
                }
        }

        // ---- bias + scale + mask + online softmax ----
        const int kvloc = tx * 4;
        float alphas[4];
#pragma unroll
        for (int r = 0; r < 4; r++) {
            float s[4];
            { float2 a = up2(s2[r][0]); float2 bq = up2(s2[r][1]);
              s[0] = a.x; s[1] = a.y; s[2] = bq.x; s[3] = bq.y; }
            float pv[4];
            const float* pp = pbase + (size_t)(ty * 4 + r) * LKV + kv0 + kvloc;
            if (kv0 + kvloc + 3 < LKV) {
                *(float4*)pv = *(const float4*)pp;
            } else {
#pragma unroll
                for (int c = 0; c < 4; c++)
                    pv[c] = (kv0 + kvloc + c < LKV) ? pp[c] : 0.0f;
            }
#pragma unroll
            for (int c = 0; c < 4; c++) {
                bool valid = (kv0 + kvloc + c) < LKV;
                s[c] = valid ? fmaf(s[c], ATTN_SCALE, pv[c]) : -1e30f;
            }
            float mt = fmaxf(fmaxf(s[0], s[1]), fmaxf(s[2], s[3]));
#pragma unroll
            for (int off = 1; off < 16; off <<= 1)
                mt = fmaxf(mt, __shfl_xor_sync(0xffffffffu, mt, off));
            float mnew  = fmaxf(m_r[r], mt);
            float alpha = __expf(m_r[r] - mnew);
            m_r[r] = mnew;
            float rs = 0.0f;
#pragma unroll
            for (int c = 0; c < 4; c++) {
                float p = __expf(s[c] - mnew);
                s[c] = p;
                rs += p;
            }
#pragma unroll
            for (int off = 1; off < 16; off <<= 1)
                rs += __shfl_xor_sync(0xffffffffu, rs, off);
            l_r[r] = l_r[r] * alpha + rs;
            alphas[r] = alpha;
            *(float4*)&Ps[ty * 4 + r][tx * 4] = make_float4(s[0], s[1], s[2], s[3]);
        }
        {
            u64 al01 = pk2(alphas[0], alphas[1]);
            u64 al23 = pk2(alphas[2], alphas[3]);
#pragma unroll
            for (int c = 0; c < 3; c++) {
                O2[0][c] = mul2(O2[0][c], al01);
                O2[1][c] = mul2(O2[1][c], al23);
            }
        }
        __syncthreads();  // Ps visible; K reads done -> KVT reusable

        // Store V transposed: KVT[d][kv]
#pragma unroll
        for (int l = 0; l < 3; l++) {
            KVT[cc[l] + 0][rr[l]] = vf4[l].x;
            KVT[cc[l] + 1][rr[l]] = vf4[l].y;
            KVT[cc[l] + 2][rr[l]] = vf4[l].z;
            KVT[cc[l] + 3][rr[l]] = vf4[l].w;
        }
        __syncthreads();

        // ---- O += P @ V  (2 row-pairs x 3 cols per thread, FFMA2) ----
#pragma unroll
        for (int k4 = 0; k4 < 16; k4++) {
            float pf[4][4], vv[3][4];
#pragma unroll
            for (int r = 0; r < 4; r++)
                *(float4*)pf[r] = *(const float4*)&Ps[ty * 4 + r][k4 * 4];
#pragma unroll
            for (int c = 0; c < 3; c++)
                *(float4*)vv[c] = *(const float4*)&KVT[tx * 3 + c][k4 * 4];
#pragma unroll
            for (int k = 0; k < 4; k++) {
                u64 p01 = pk2(pf[0][k], pf[1][k]);
                u64 p23 = pk2(pf[2][k], pf[3][k]);
#pragma unroll
                for (int c = 0; c < 3; c++) {
                    u64 vd = dup2(vv[c][k]);
                    O2[0][c] = fma2(p01, vd, O2[0][c]);
                    O2[1][c] = fma2(p23, vd, O2[1][c]);
                }
            }
        }
    }

    // ---- normalize + write x (b, q, h*48+d) ----
    float inv[4];
#pragma unroll
    for (int r = 0; r < 4; r++) inv[r] = 1.0f / l_r[r];
#pragma unroll
    for (int p = 0; p < 2; p++) {
        int r0 = p * 2, r1 = p * 2 + 1;
        float* xp0 = g_x + ((size_t)(b * LQ + q0 + ty * 4 + r0)) * DIM + h * HD + tx * 3;
        float* xp1 = g_x + ((size_t)(b * LQ + q0 + ty * 4 + r1)) * DIM + h * HD + tx * 3;
#pragma unroll
        for (int c = 0; c < 3; c++) {
            float2 o = up2(O2[p][c]);
            xp0[c] = o.x * inv[r0];
            xp1[c] = o.y * inv[r1];
        }
    }
}

// ---------------------------------------------------------------------------
// Launch
// ---------------------------------------------------------------------------
extern "C" void kernel_launch(void* const* d_in, const int* in_sizes, int n_in,
                              void* d_out, int out_size)
{
    const float* tem_mask    = (const float*)d_in[0];
    const float* search_mask = (const float*)d_in[1];
    const float* q           = (const float*)d_in[2];
    const float* kv          = (const float*)d_in[3];
    const float* attn_pos    = (const float*)d_in[4];
    const float* q_w         = (const float*)d_in[5];
    const float* q_b         = (const float*)d_in[6];
    const float* kv_w        = (const float*)d_in[7];
    const float* kv_b        = (const float*)d_in[8];
    const float* proj_w      = (const float*)d_in[9];
    const float* proj_b      = (const float*)d_in[10];
    float* out = (float*)d_out;

    // q projection: (16*1024, 384) @ (384, 384)^T   -> g_qh
    sgemm_kernel<0><<<dim3(3, 128), 256>>>(q, q_w, q_b, nullptr, nullptr, nullptr);
    // kv projection: (16*1424, 384) @ (768, 384)^T  -> g_kh / g_vh (+masks)
    sgemm_kernel<1><<<dim3(6, 178), 256>>>(kv, kv_w, kv_b, tem_mask, search_mask, nullptr);
    // flash attention with bias                      -> g_x
    attn_kernel<<<B * H * (LQ / 64), 256>>>(attn_pos);
    // output projection: (16*1024, 384) @ (384,384)^T -> d_out
    sgemm_kernel<2><<<dim3(3, 128), 256>>>(nullptr, proj_w, proj_b, nullptr, nullptr, out);
}

// round 5
// speedup vs baseline: 1.0011x; 1.0010x over previous
#include <cuda_runtime.h>

// ---------------------------------------------------------------------------
// searchMaskCrossAttention: fused QKV projection + flash cross-attention with
// additive position bias + output projection.  All fp32 math, but the inner
// products use Blackwell packed fp32 (fma.rn.f32x2 -> SASS FFMA2) for 2x the
// scalar-FFMA issue rate.
//   B=16, Lq=1024, Lkv=1424, DIM=384, HEADS=8, HEAD_DIM=48, TEM_LEN=400
// ---------------------------------------------------------------------------

constexpr int B    = 16;
constexpr int H    = 8;
constexpr int DIM  = 384;
constexpr int HD   = 48;
constexpr int LQ   = 1024;
constexpr int LKV  = 1424;
constexpr int TEM  = 400;
constexpr float ATTN_SCALE = 0.14433756729740643f;  // 48^-0.5

using u64 = unsigned long long;

// ---- packed fp32 (f32x2) helpers: sm_100+ ---------------------------------
__device__ __forceinline__ u64 pk2(float lo, float hi) {
    u64 d; asm("mov.b64 %0, {%1, %2};" : "=l"(d) : "f"(lo), "f"(hi)); return d;
}
__device__ __forceinline__ u64 dup2(float x) { return pk2(x, x); }
__device__ __forceinline__ u64 fma2(u64 a, u64 b, u64 c) {
    u64 d; asm("fma.rn.f32x2 %0, %1, %2, %3;" : "=l"(d) : "l"(a), "l"(b), "l"(c));
    return d;
}
__device__ __forceinline__ u64 mul2(u64 a, u64 b) {
    u64 d; asm("mul.rn.f32x2 %0, %1, %2;" : "=l"(d) : "l"(a), "l"(b)); return d;
}
__device__ __forceinline__ float2 up2(u64 d) {
    float2 r; asm("mov.b64 {%0, %1}, %2;" : "=f"(r.x), "=f"(r.y) : "l"(d)); return r;
}

// Scratch (device globals: allocation-free under harness rules)
__device__ float g_qh[B * H * LQ * HD];    // (b,h,q,d)
__device__ float g_kh[B * H * LKV * HD];   // (b,h,s,d)
__device__ float g_vh[B * H * LKV * HD];   // (b,h,s,d)
__device__ float g_x [B * LQ * DIM];       // (b,q,h*48+d)

// ---------------------------------------------------------------------------
// SGEMM: out[m][n] = sum_k A[m][k] * W[n][k] + bias[n], K = 384 fixed.
// Block tile 128x128, BK=16, 256 threads, 8x8 microtile (f32x2: 8x4 pairs).
// ---------------------------------------------------------------------------
template <int MODE>
__global__ __launch_bounds__(256) void sgemm_kernel(
    const float* __restrict__ A, const float* __restrict__ W,
    const float* __restrict__ bias,
    const float* __restrict__ tmask, const float* __restrict__ smask,
    float* __restrict__ out)
{
    __shared__ __align__(16) float As[16][128];
    __shared__ __align__(16) float Bs[16][128];

    const int m0  = blockIdx.y * 128;
    const int n0  = blockIdx.x * 128;
    const int tid = threadIdx.x;
    const int tx  = tid & 15;
    const int ty  = tid >> 4;

    u64 acc2[8][4];
#pragma unroll
    for (int i = 0; i < 8; i++)
#pragma unroll
        for (int j = 0; j < 4; j++) acc2[i][j] = 0ull;

    const float* Aptr = (MODE == 2) ? (&g_x[0] + (size_t)m0 * DIM)
                                    : (A + (size_t)m0 * DIM);
    const float* Wptr = W + (size_t)n0 * DIM;

    for (int k0 = 0; k0 < DIM; k0 += 16) {
#pragma unroll
        for (int l = 0; l < 2; l++) {
            int idx = tid + 256 * l;
            int row = idx >> 2;            // 0..127
            int c4  = (idx & 3) << 2;      // 0,4,8,12
            float4 a = *(const float4*)(Aptr + (size_t)row * DIM + k0 + c4);
            As[c4 + 0][row] = a.x; As[c4 + 1][row] = a.y;
            As[c4 + 2][row] = a.z; As[c4 + 3][row] = a.w;
            float4 b = *(const float4*)(Wptr + (size_t)row * DIM + k0 + c4);
            Bs[c4 + 0][row] = b.x; Bs[c4 + 1][row] = b.y;
            Bs[c4 + 2][row] = b.z; Bs[c4 + 3][row] = b.w;
        }
        __syncthreads();
#pragma unroll
        for (int kk = 0; kk < 16; kk++) {
            float af[8];
            u64   bp[4];
            *(float4*)&af[0] = *(const float4*)&As[kk][ty * 8];
            *(float4*)&af[4] = *(const float4*)&As[kk][ty * 8 + 4];
            ulonglong2 b01 = *(const ulonglong2*)&Bs[kk][tx * 8];
            ulonglong2 b23 = *(const ulonglong2*)&Bs[kk][tx * 8 + 4];
            bp[0] = b01.x; bp[1] = b01.y; bp[2] = b23.x; bp[3] = b23.y;
#pragma unroll
            for (int i = 0; i < 8; i++) {
                u64 ad = dup2(af[i]);
#pragma unroll
                for (int j = 0; j < 4; j++)
                    acc2[i][j] = fma2(ad, bp[j], acc2[i][j]);
            }
        }
        __syncthreads();
    }

    // Epilogue
#pragma unroll
    for (int i = 0; i < 8; i++) {
        int m = m0 + ty * 8 + i;
        float acc[8];
#pragma unroll
        for (int j = 0; j < 4; j++) {
            float2 v = up2(acc2[i][j]);
            acc[2 * j] = v.x; acc[2 * j + 1] = v.y;
        }
#pragma unroll
        for (int j = 0; j < 8; j++) {
            int n = n0 + tx * 8 + j;
            float v = acc[j] + bias[n];
            if (MODE == 0) {
                int b  = m >> 10;
                int qi = m & 1023;
                int h  = n / HD;
                int d  = n - h * HD;
                g_qh[((b * H + h) * LQ + qi) * HD + d] = v;
            } else if (MODE == 1) {
                int b = m / LKV;
                int s = m - b * LKV;
                if (n < DIM) {
                    int h = n / HD, d = n - h * HD;
                    g_kh[((b * H + h) * LKV + s) * HD + d] = v;
                } else {
                    int nv = n - DIM;
                    float mv = (s < TEM)
                        ? tmask[((size_t)(b * TEM + s)) * DIM + nv]
                        : smask[((size_t)(b * (LKV - TEM) + (s - TEM))) * DIM + nv];
                    v += mv;
                    int h = nv / HD, d = nv - h * HD;
                    g_vh[((b * H + h) * LKV + s) * HD + d] = v;
                }
            } else {
                out[(size_t)m * DIM + n] = v;
            }
        }
    }
}

// ---------------------------------------------------------------------------
// Flash attention with additive bias.  Block: one (b, h, q-tile of 64),
// 256 threads = 16x16.  S-phase 4x4 per thread (f32x2 pairs over kv-cols),
// PV-phase 4x3 per thread (f32x2 pairs over q-rows).
// ---------------------------------------------------------------------------
__global__ __launch_bounds__(256, 2) void attn_kernel(const float* __restrict__ pos)
{
    __shared__ __align__(16) float Qs [64][52];  // [q][d]
    __shared__ __align__(16) float KVT[48][68];  // [d][kv]  (K, then V)
    __shared__ __align__(16) float Ps [64][68];  // [q][kv]

    const int bid = blockIdx.x;
    const int b   = bid & 15;          // batch fastest -> attn_pos reuse in L2
    const int qt  = (bid >> 4) & 15;
    const int h   = bid >> 8;
    const int tid = threadIdx.x;
    const int tx  = tid & 15;
    const int ty  = tid >> 4;
    const int q0  = qt * 64;

    // Load Q tile (64 x 48)
    const float* qbase = g_qh + ((size_t)((b * H + h) * LQ + q0)) * HD;
#pragma unroll
    for (int l = 0; l < 3; l++) {
        int i  = tid + 256 * l;
        int r  = i / 12;
        int c4 = (i % 12) * 4;
        *(float4*)&Qs[r][c4] = *(const float4*)(qbase + (size_t)r * HD + c4);
    }

    const float* kbase = g_kh + ((size_t)((b * H + h)) * LKV) * HD;
    const float* vbase = g_vh + ((size_t)((b * H + h)) * LKV) * HD;
    const float* pbase = pos + ((size_t)h * LQ + q0) * (size_t)LKV;

    float m_r[4], l_r[4];
    u64 O2[2][3];                       // [q-row pair][out col], rows (ty*4+2p, +2p+1)
#pragma unroll
    for (int r = 0; r < 4; r++) { m_r[r] = -1e30f; l_r[r] = 0.0f; }
#pragma unroll
    for (int p = 0; p < 2; p++)
#pragma unroll
        for (int c = 0; c < 3; c++) O2[p][c] = 0ull;

    constexpr int NT = (LKV + 63) / 64;  // 23 (last tile has 16 valid rows)

    for (int t = 0; t < NT; t++) {
        const int kv0 = t * 64;

        // Issue global K/V loads into registers (overlaps with sync/compute)
        float4 kf4[3], vf4[3];
        int rr[3], cc[3];
#pragma unroll
        for (int l = 0; l < 3; l++) {
            int i  = tid + 256 * l;
            int r  = i / 12;
            int c4 = (i % 12) * 4;
            rr[l] = r; cc[l] = c4;
            int row = kv0 + r;
            if (row < LKV) {
                kf4[l] = *(const float4*)(kbase + (size_t)row * HD + c4);
                vf4[l] = *(const float4*)(vbase + (size_t)row * HD + c4);
            } else {
                kf4[l] = make_float4(0.f, 0.f, 0.f, 0.f);
                vf4[l] = make_float4(0.f, 0.f, 0.f, 0.f);
            }
        }
        __syncthreads();  // previous tile's P@V (and Q load on t=0) complete

        // Store K transposed: KVT[d][kv]
#pragma unroll
        for (int l = 0; l < 3; l++) {
            KVT[cc[l] + 0][rr[l]] = kf4[l].x;
            KVT[cc[l] + 1][rr[l]] = kf4[l].y;
            KVT[cc[l] + 2][rr[l]] = kf4[l].z;
            KVT[cc[l] + 3][rr[l]] = kf4[l].w;
        }
        __syncthreads();

        // ---- S = Q @ K^T  (4 rows x 2 col-pairs per thread, FFMA2) ----
        u64 s2[4][2];
#pragma unroll
        for (int r = 0; r < 4; r++) { s2[r][0] = 0ull; s2[r][1] = 0ull; }

#pragma unroll
        for (int d4 = 0; d4 < 12; d4++) {
            float qv[4][4];
            u64   kp[4][2];
#pragma unroll
            for (int j = 0; j < 4; j++) {
                ulonglong2 kt = *(const ulonglong2*)&KVT[d4 * 4 + j][tx * 4];
                kp[j][0] = kt.x; kp[j][1] = kt.y;
            }
#pragma unroll
            for (int r = 0; r < 4; r++)
                *(float4*)qv[r] = *(const float4*)&Qs[ty * 4 + r][d4 * 4];
#pragma unroll
            for (int r = 0; r < 4; r++)
#pragma unroll
                for (int j = 0; j < 4; j++) {
                    u64 qd = dup2(qv[r][j]);
                    s2[r][0] = fma2(qd, kp[j][0], s2[r][0]);
                    s2[r][1] = fma2(qd, kp[j][1], s2[r][1]);
                }
        }

        // ---- bias + scale + mask + online softmax ----
        const int kvloc = tx * 4;
        float alphas[4];
#pragma unroll
        for (int r = 0; r < 4; r++) {
            float s[4];
            { float2 a = up2(s2[r][0]); float2 bq = up2(s2[r][1]);
              s[0] = a.x; s[1] = a.y; s[2] = bq.x; s[3] = bq.y; }
            float pv[4];
            const float* pp = pbase + (size_t)(ty * 4 + r) * LKV + kv0 + kvloc;
            if (kv0 + kvloc + 3 < LKV) {
                *(float4*)pv = *(const float4*)pp;
            } else {
#pragma unroll
                for (int c = 0; c < 4; c++)
                    pv[c] = (kv0 + kvloc + c < LKV) ? pp[c] : 0.0f;
            }
#pragma unroll
            for (int c = 0; c < 4; c++) {
                bool valid = (kv0 + kvloc + c) < LKV;
                s[c] = valid ? fmaf(s[c], ATTN_SCALE, pv[c]) : -1e30f;
            }
            float mt = fmaxf(fmaxf(s[0], s[1]), fmaxf(s[2], s[3]));
#pragma unroll
            for (int off = 1; off < 16; off <<= 1)
                mt = fmaxf(mt, __shfl_xor_sync(0xffffffffu, mt, off));
            float mnew  = fmaxf(m_r[r], mt);
            float alpha = __expf(m_r[r] - mnew);
            m_r[r] = mnew;
            float rs = 0.0f;
#pragma unroll
            for (int c = 0; c < 4; c++) {
                float p = __expf(s[c] - mnew);
                s[c] = p;
                rs += p;
            }
#pragma unroll
            for (int off = 1; off < 16; off <<= 1)
                rs += __shfl_xor_sync(0xffffffffu, rs, off);
            l_r[r] = l_r[r] * alpha + rs;
            alphas[r] = alpha;
            *(float4*)&Ps[ty * 4 + r][tx * 4] = make_float4(s[0], s[1], s[2], s[3]);
        }
        {
            u64 al01 = pk2(alphas[0], alphas[1]);
            u64 al23 = pk2(alphas[2], alphas[3]);
#pragma unroll
            for (int c = 0; c < 3; c++) {
                O2[0][c] = mul2(O2[0][c], al01);
                O2[1][c] = mul2(O2[1][c], al23);
            }
        }
        __syncthreads();  // Ps visible; K reads done -> KVT reusable

        // Store V transposed: KVT[d][kv]
#pragma unroll
        for (int l = 0; l < 3; l++) {
            KVT[cc[l] + 0][rr[l]] = vf4[l].x;
            KVT[cc[l] + 1][rr[l]] = vf4[l].y;
            KVT[cc[l] + 2][rr[l]] = vf4[l].z;
            KVT[cc[l] + 3][rr[l]] = vf4[l].w;
        }
        __syncthreads();

        // ---- O += P @ V  (2 row-pairs x 3 cols per thread, FFMA2) ----
#pragma unroll
        for (int k4 = 0; k4 < 16; k4++) {
            float pf[4][4], vv[3][4];
#pragma unroll
            for (int r = 0; r < 4; r++)
                *(float4*)pf[r] = *(const float4*)&Ps[ty * 4 + r][k4 * 4];
#pragma unroll
            for (int c = 0; c < 3; c++)
                *(float4*)vv[c] = *(const float4*)&KVT[tx * 3 + c][k4 * 4];
#pragma unroll
            for (int k = 0; k < 4; k++) {
                u64 p01 = pk2(pf[0][k], pf[1][k]);
                u64 p23 = pk2(pf[2][k], pf[3][k]);
#pragma unroll
                for (int c = 0; c < 3; c++) {
                    u64 vd = dup2(vv[c][k]);
                    O2[0][c] = fma2(p01, vd, O2[0][c]);
                    O2[1][c] = fma2(p23, vd, O2[1][c]);
                }
            }
        }
    }

    // ---- normalize + write x (b, q, h*48+d) ----
    float inv[4];
#pragma unroll
    for (int r = 0; r < 4; r++) inv[r] = 1.0f / l_r[r];
#pragma unroll
    for (int p = 0; p < 2; p++) {
        int r0 = p * 2, r1 = p * 2 + 1;
        float* xp0 = g_x + ((size_t)(b * LQ + q0 + ty * 4 + r0)) * DIM + h * HD + tx * 3;
        float* xp1 = g_x + ((size_t)(b * LQ + q0 + ty * 4 + r1)) * DIM + h * HD + tx * 3;
#pragma unroll
        for (int c = 0; c < 3; c++) {
            float2 o = up2(O2[p][c]);
            xp0[c] = o.x * inv[r0];
            xp1[c] = o.y * inv[r1];
        }
    }
}

// ---------------------------------------------------------------------------
// Launch
// ---------------------------------------------------------------------------
extern "C" void kernel_launch(void* const* d_in, const int* in_sizes, int n_in,
                              void* d_out, int out_size)
{
    const float* tem_mask    = (const float*)d_in[0];
    const float* search_mask = (const float*)d_in[1];
    const float* q           = (const float*)d_in[2];
    const float* kv          = (const float*)d_in[3];
    const float* attn_pos    = (const float*)d_in[4];
    const float* q_w         = (const float*)d_in[5];
    const float* q_b         = (const float*)d_in[6];
    const float* kv_w        = (const float*)d_in[7];
    const float* kv_b        = (const float*)d_in[8];
    const float* proj_w      = (const float*)d_in[9];
    const float* proj_b      = (const float*)d_in[10];
    float* out = (float*)d_out;

    // q projection: (16*1024, 384) @ (384, 384)^T   -> g_qh
    sgemm_kernel<0><<<dim3(3, 128), 256>>>(q, q_w, q_b, nullptr, nullptr, nullptr);
    // kv projection: (16*1424, 384) @ (768, 384)^T  -> g_kh / g_vh (+masks)
    sgemm_kernel<1><<<dim3(6, 178), 256>>>(kv, kv_w, kv_b, tem_mask, search_mask, nullptr);
    // flash attention with bias                      -> g_x
    attn_kernel<<<B * H * (LQ / 64), 256>>>(attn_pos);
    // output projection: (16*1024, 384) @ (384,384)^T -> d_out
    sgemm_kernel<2><<<dim3(3, 128), 256>>>(nullptr, proj_w, proj_b, nullptr, nullptr, out);
}

// round 8
// speedup vs baseline: 1.5354x; 1.5338x over previous
#include <cuda_runtime.h>
#include <cuda_bf16.h>
#include <stdint.h>

// ---------------------------------------------------------------------------
// B=16, Lq=1024, Lkv=1424, DIM=384, HEADS=8, HEAD_DIM=48, TEM_LEN=400
// projections: SIMT FFMA2 SGEMM (epilogues emit bf16 hi/lo attention operands)
// attention:   mma.sync.m16n8k16 bf16 (hi/lo 3-product splits), fixed-max
//              softmax, O in registers across all kv tiles (no rescale)
// out proj:    SIMT FFMA2 SGEMM fp32
// ---------------------------------------------------------------------------

constexpr int B    = 16;
constexpr int H    = 8;
constexpr int DIM  = 384;
constexpr int HD   = 48;
constexpr int LQ   = 1024;
constexpr int LKV  = 1424;
constexpr int TEM  = 400;
constexpr float ATTN_SCALE = 0.14433756729740643f;  // 48^-0.5
constexpr float M_FIX = 12.0f;

using u64 = unsigned long long;
using u32 = unsigned int;

// ---- packed fp32 helpers (sgemm inner loop) --------------------------------
__device__ __forceinline__ u64 pk2(float lo, float hi) {
    u64 d; asm("mov.b64 %0, {%1, %2};" : "=l"(d) : "f"(lo), "f"(hi)); return d;
}
__device__ __forceinline__ u64 dup2(float x) { return pk2(x, x); }
__device__ __forceinline__ u64 fma2(u64 a, u64 b, u64 c) {
    u64 d; asm("fma.rn.f32x2 %0, %1, %2, %3;" : "=l"(d) : "l"(a), "l"(b), "l"(c));
    return d;
}
__device__ __forceinline__ float2 up2(u64 d) {
    float2 r; asm("mov.b64 {%0, %1}, %2;" : "=f"(r.x), "=f"(r.y) : "l"(d)); return r;
}

// ---- scratch ---------------------------------------------------------------
__device__ __nv_bfloat16 g_qhi[B * H * LQ * HD];    // (b,h,q,d) pre-scaled
__device__ __nv_bfloat16 g_qlo[B * H * LQ * HD];
__device__ __nv_bfloat16 g_khi[B * H * LKV * HD];   // (b,h,s,d)
__device__ __nv_bfloat16 g_klo[B * H * LKV * HD];
__device__ __nv_bfloat16 g_vthi[B * H * HD * LKV];  // (b,h,d,s) transposed
__device__ __nv_bfloat16 g_vtlo[B * H * HD * LKV];
__device__ float g_x[B * LQ * DIM];

// ---- mma.sync / ldmatrix wrappers (baseline PTX, sm_80+) -------------------
__device__ __forceinline__ u32 smu32(const void* p) {
    u32 a;
    asm("{ .reg .u64 t; cvta.to.shared.u64 t, %1; cvt.u32.u64 %0, t; }"
        : "=r"(a) : "l"(p));
    return a;
}
__device__ __forceinline__ void ldmx4(u32* r, u32 addr) {
    asm volatile("ldmatrix.sync.aligned.m8n8.x4.shared.b16 {%0,%1,%2,%3}, [%4];"
                 : "=r"(r[0]), "=r"(r[1]), "=r"(r[2]), "=r"(r[3]) : "r"(addr));
}
__device__ __forceinline__ void ldmx2(u32* r, u32 addr) {
    asm volatile("ldmatrix.sync.aligned.m8n8.x2.shared.b16 {%0,%1}, [%2];"
                 : "=r"(r[0]), "=r"(r[1]) : "r"(addr));
}
__device__ __forceinline__ void mma16816(float* d, const u32* a, const u32* b) {
    asm volatile(
        "mma.sync.aligned.m16n8k16.row.col.f32.bf16.bf16.f32 "
        "{%0,%1,%2,%3}, {%4,%5,%6,%7}, {%8,%9}, {%0,%1,%2,%3};"
        : "+f"(d[0]), "+f"(d[1]), "+f"(d[2]), "+f"(d[3])
        : "r"(a[0]), "r"(a[1]), "r"(a[2]), "r"(a[3]), "r"(b[0]), "r"(b[1]));
}
// pack (lo, hi) floats -> bf16x2 register (lo -> lower 16 bits)
__device__ __forceinline__ u32 cvt2bf(float lo, float hi) {
    u32 d; asm("cvt.rn.bf16x2.f32 %0, %1, %2;" : "=r"(d) : "f"(hi), "f"(lo));
    return d;
}

// ---------------------------------------------------------------------------
// SGEMM (FFMA2).  MODE 0: q-proj -> g_qhi/lo (pre-scaled).
//                 MODE 1: kv-proj -> g_khi/lo + g_vthi/lo (+masks, transposed)
//                 MODE 2: out-proj (fp32, reads g_x)
// ---------------------------------------------------------------------------
template <int MODE>
__global__ __launch_bounds__(256) void sgemm_kernel(
    const float* __restrict__ A, const float* __restrict__ W,
    const float* __restrict__ bias,
    const float* __restrict__ tmask, const float* __restrict__ smask,
    float* __restrict__ out)
{
    __shared__ __align__(16) float As[16][128];
    __shared__ __align__(16) float Bs[16][128];

    const int m0  = blockIdx.y * 128;
    const int n0  = blockIdx.x * 128;
    const int tid = threadIdx.x;
    const int tx  = tid & 15;
    const int ty  = tid >> 4;

    u64 acc2[8][4];
#pragma unroll
    for (int i = 0; i < 8; i++)
#pragma unroll
        for (int j = 0; j < 4; j++) acc2[i][j] = 0ull;

    const float* Aptr = (MODE == 2) ? (&g_x[0] + (size_t)m0 * DIM)
                                    : (A + (size_t)m0 * DIM);
    const float* Wptr = W + (size_t)n0 * DIM;

    for (int k0 = 0; k0 < DIM; k0 += 16) {
#pragma unroll
        for (int l = 0; l < 2; l++) {
            int idx = tid + 256 * l;
            int row = idx >> 2;
            int c4  = (idx & 3) << 2;
            float4 a = *(const float4*)(Aptr + (size_t)row * DIM + k0 + c4);
            As[c4 + 0][row] = a.x; As[c4 + 1][row] = a.y;
            As[c4 + 2][row] = a.z; As[c4 + 3][row] = a.w;
            float4 b = *(const float4*)(Wptr + (size_t)row * DIM + k0 + c4);
            Bs[c4 + 0][row] = b.x; Bs[c4 + 1][row] = b.y;
            Bs[c4 + 2][row] = b.z; Bs[c4 + 3][row] = b.w;
        }
        __syncthreads();
#pragma unroll
        for (int kk = 0; kk < 16; kk++) {
            float af[8]; u64 bp[4];
            *(float4*)&af[0] = *(const float4*)&As[kk][ty * 8];
            *(float4*)&af[4] = *(const float4*)&As[kk][ty * 8 + 4];
            ulonglong2 b01 = *(const ulonglong2*)&Bs[kk][tx * 8];
            ulonglong2 b23 = *(const ulonglong2*)&Bs[kk][tx * 8 + 4];
            bp[0] = b01.x; bp[1] = b01.y; bp[2] = b23.x; bp[3] = b23.y;
#pragma unroll
            for (int i = 0; i < 8; i++) {
                u64 ad = dup2(af[i]);
#pragma unroll
                for (int j = 0; j < 4; j++)
                    acc2[i][j] = fma2(ad, bp[j], acc2[i][j]);
            }
        }
        __syncthreads();
    }

#pragma unroll
    for (int i = 0; i < 8; i++) {
        int m = m0 + ty * 8 + i;
        float acc[8];
#pragma unroll
        for (int j = 0; j < 4; j++) {
            float2 v = up2(acc2[i][j]);
            acc[2 * j] = v.x; acc[2 * j + 1] = v.y;
        }
#pragma unroll
        for (int j = 0; j < 8; j++) {
            int n = n0 + tx * 8 + j;
            float v = acc[j] + bias[n];
            if (MODE == 0) {
                int b  = m >> 10;
                int qi = m & 1023;
                int h  = n / HD;
                int d  = n - h * HD;
                float vs = v * ATTN_SCALE;
                __nv_bfloat16 hb = __float2bfloat16(vs);
                float lo = vs - __bfloat162float(hb);
                size_t o = ((size_t)(b * H + h) * LQ + qi) * HD + d;
                g_qhi[o] = hb;
                g_qlo[o] = __float2bfloat16(lo);
            } else if (MODE == 1) {
                int b = m / LKV;
                int s = m - b * LKV;
                if (n < DIM) {
                    int h = n / HD, d = n - h * HD;
                    __nv_bfloat16 hb = __float2bfloat16(v);
                    float lo = v - __bfloat162float(hb);
                    size_t o = ((size_t)(b * H + h) * LKV + s) * HD + d;
                    g_khi[o] = hb;
                    g_klo[o] = __float2bfloat16(lo);
                } else {
                    int nv = n - DIM;
                    float mv = (s < TEM)
                        ? tmask[((size_t)(b * TEM + s)) * DIM + nv]
                        : smask[((size_t)(b * (LKV - TEM) + (s - TEM))) * DIM + nv];
                    v += mv;
                    int h = nv / HD, d = nv - h * HD;
                    __nv_bfloat16 hb = __float2bfloat16(v);
                    float lo = v - __bfloat162float(hb);
                    size_t o = ((size_t)(b * H + h) * HD + d) * LKV + s;
                    g_vthi[o] = hb;
                    g_vtlo[o] = __float2bfloat16(lo);
                }
            } else {
                out[(size_t)m * DIM + n] = v;
            }
        }
    }
}

// ---------------------------------------------------------------------------
// mma.sync flash attention.  Block = (b, h, 64-q tile), 128 threads (4 warps),
// each warp owns 16 q rows.  kv tiles of 64.
// ---------------------------------------------------------------------------
constexpr int QK_STRIDE = 56;   // bf16 elems; 112B rows -> conflict-free ldmatrix
constexpr int V_STRIDE  = 72;   // 144B rows

__global__ __launch_bounds__(128) void attn_kernel(const float* __restrict__ pos)
{
    __shared__ __align__(16) __nv_bfloat16 Qh[64][QK_STRIDE];
    __shared__ __align__(16) __nv_bfloat16 Ql[64][QK_STRIDE];
    __shared__ __align__(16) __nv_bfloat16 Kh[64][QK_STRIDE];
    __shared__ __align__(16) __nv_bfloat16 Kl[64][QK_STRIDE];
    __shared__ __align__(16) __nv_bfloat16 Vh[48][V_STRIDE];
    __shared__ __align__(16) __nv_bfloat16 Vl[48][V_STRIDE];

    const int tid   = threadIdx.x;
    const int warp  = tid >> 5;
    const int lane  = tid & 31;
    const int l16   = lane & 15;
    const int bid   = blockIdx.x;
    const int b     = bid & 15;            // batch fastest: pos L2 reuse x16
    const int qt    = (bid >> 4) & 15;
    const int h     = bid >> 8;
    const int q0    = qt * 64;
    const int bh    = b * H + h;
    const int qrow0 = warp * 16;

    const u32 sQh = smu32(&Qh[0][0]), sQl = smu32(&Ql[0][0]);
    const u32 sKh = smu32(&Kh[0][0]), sKl = smu32(&Kl[0][0]);
    const u32 sVh = smu32(&Vh[0][0]), sVl = smu32(&Vl[0][0]);

    // ---- fill Q tile (64 x 48) hi/lo ----
    {
        const __nv_bfloat16* qh = g_qhi + ((size_t)bh * LQ + q0) * HD;
        const __nv_bfloat16* ql = g_qlo + ((size_t)bh * LQ + q0) * HD;
#pragma unroll
        for (int l = 0; l < 3; l++) {
            int idx = tid + 128 * l;
            int row = idx / 6, c = idx % 6;
            *(uint4*)&Qh[row][c * 8] = *(const uint4*)(qh + row * HD + c * 8);
            *(uint4*)&Ql[row][c * 8] = *(const uint4*)(ql + row * HD + c * 8);
        }
    }
    __syncthreads();

    // ---- Q fragments (held in registers for all kv tiles) ----
    u32 qfh[3][4], qfl[3][4];
    {
        u32 qoff = (u32)((qrow0 + l16) * (QK_STRIDE * 2) + (lane >> 4) * 16);
#pragma unroll
        for (int ks = 0; ks < 3; ks++) {
            ldmx4(qfh[ks], sQh + qoff + ks * 32);
            ldmx4(qfl[ks], sQl + qoff + ks * 32);
        }
    }

    const __nv_bfloat16* kh = g_khi + (size_t)bh * LKV * HD;
    const __nv_bfloat16* kl = g_klo + (size_t)bh * LKV * HD;
    const __nv_bfloat16* vh = g_vthi + (size_t)bh * HD * LKV;
    const __nv_bfloat16* vl = g_vtlo + (size_t)bh * HD * LKV;

    const int rowA = q0 + qrow0 + (lane >> 2);
    const float* posA = pos + ((size_t)h * LQ + rowA) * LKV;
    const float* posB = posA + (size_t)8 * LKV;

    float oacc[6][4];
#pragma unroll
    for (int n = 0; n < 6; n++)
#pragma unroll
        for (int j = 0; j < 4; j++) oacc[n][j] = 0.0f;
    float lsum0 = 0.0f, lsum1 = 0.0f;

    constexpr int NT = (LKV + 63) / 64;  // 23

    for (int t = 0; t < NT; t++) {
        const int kv0 = t * 64;

        __syncthreads();   // previous tile's smem reads done

        // ---- fill K (64 x 48) and V^T (48 x 64) hi/lo ----
#pragma unroll
        for (int l = 0; l < 3; l++) {
            int idx = tid + 128 * l;
            int row = idx / 6, c = idx % 6;
            int srow = kv0 + row; if (srow >= LKV) srow = LKV - 1;
            *(uint4*)&Kh[row][c * 8] = *(const uint4*)(kh + (size_t)srow * HD + c * 8);
            *(uint4*)&Kl[row][c * 8] = *(const uint4*)(kl + (size_t)srow * HD + c * 8);
        }
#pragma unroll
        for (int l = 0; l < 3; l++) {
            int idx = tid + 128 * l;
            int row = idx / 8, c = idx % 8;
            int skv = kv0 + c * 8; if (skv + 8 > LKV) skv = LKV - 8;
            *(uint4*)&Vh[row][c * 8] = *(const uint4*)(vh + (size_t)row * LKV + skv);
            *(uint4*)&Vl[row][c * 8] = *(const uint4*)(vl + (size_t)row * LKV + skv);
        }
        __syncthreads();

        // ---- S = Qhi.Khi + Qlo.Khi + Qhi.Klo ----
        float sacc[8][4];
#pragma unroll
        for (int n = 0; n < 8; n++)
#pragma unroll
            for (int j = 0; j < 4; j++) sacc[n][j] = 0.0f;

#pragma unroll
        for (int nn = 0; nn < 8; nn++) {
            u32 koff = (u32)((nn * 8 + (l16 & 7)) * (QK_STRIDE * 2) + (l16 >> 3) * 16);
#pragma unroll
            for (int ks = 0; ks < 3; ks++) {
                u32 bh2[2], bl2[2];
                ldmx2(bh2, sKh + koff + ks * 32);
                ldmx2(bl2, sKl + koff + ks * 32);
                mma16816(sacc[nn], qfh[ks], bh2);
                mma16816(sacc[nn], qfl[ks], bh2);
                mma16816(sacc[nn], qfh[ks], bl2);
            }
        }

        // ---- softmax: p = exp(s + pos - M_FIX), fixed max (exact) ----
#pragma unroll
        for (int nn = 0; nn < 8; nn++) {
            int col = kv0 + nn * 8 + (lane & 3) * 2;
            if (col < LKV) {
                float2 pA = *(const float2*)(posA + col);
                float2 pB = *(const float2*)(posB + col);
                float p0 = __expf(sacc[nn][0] + pA.x - M_FIX);
                float p1 = __expf(sacc[nn][1] + pA.y - M_FIX);
                float p2 = __expf(sacc[nn][2] + pB.x - M_FIX);
                float p3 = __expf(sacc[nn][3] + pB.y - M_FIX);
                sacc[nn][0] = p0; sacc[nn][1] = p1;
                sacc[nn][2] = p2; sacc[nn][3] = p3;
                lsum0 += p0 + p1;
                lsum1 += p2 + p3;
            } else {
                sacc[nn][0] = 0.f; sacc[nn][1] = 0.f;
                sacc[nn][2] = 0.f; sacc[nn][3] = 0.f;
            }
        }

        // ---- O += Phi.Vhi + Plo.Vhi + Phi.Vlo ----
#pragma unroll
        for (int kk = 0; kk < 4; kk++) {
            u32 pah[4], pal[4];
#pragma unroll
            for (int half = 0; half < 2; half++) {
                int cn = 2 * kk + half;
                float p0 = sacc[cn][0], p1 = sacc[cn][1];
                float p2 = sacc[cn][2], p3 = sacc[cn][3];
                float h0 = __bfloat162float(__float2bfloat16(p0));
                float h1 = __bfloat162float(__float2bfloat16(p1));
                float h2 = __bfloat162float(__float2bfloat16(p2));
                float h3 = __bfloat162float(__float2bfloat16(p3));
                // a0=(row g, k lo), a1=(row g+8, k lo), a2=(row g, k hi), a3=(row g+8, k hi)
                if (half == 0) {
                    pah[0] = cvt2bf(p0, p1);
                    pah[1] = cvt2bf(p2, p3);
                    pal[0] = cvt2bf(p0 - h0, p1 - h1);
                    pal[1] = cvt2bf(p2 - h2, p3 - h3);
                } else {
                    pah[2] = cvt2bf(p0, p1);
                    pah[3] = cvt2bf(p2, p3);
                    pal[2] = cvt2bf(p0 - h0, p1 - h1);
                    pal[3] = cvt2bf(p2 - h2, p3 - h3);
                }
            }
#pragma unroll
            for (int nd = 0; nd < 6; nd++) {
                u32 voff = (u32)((nd * 8 + (l16 & 7)) * (V_STRIDE * 2) + kk * 32 + (l16 >> 3) * 16);
                u32 vfh[2], vfl[2];
                ldmx2(vfh, sVh + voff);
                ldmx2(vfl, sVl + voff);
                mma16816(oacc[nd], pah, vfh);
                mma16816(oacc[nd], pal, vfh);
                mma16816(oacc[nd], pah, vfl);
            }
        }
    }

    // ---- row-sum reduce (4 lanes per row) + normalize + write ----
    lsum0 += __shfl_xor_sync(0xffffffffu, lsum0, 1);
    lsum0 += __shfl_xor_sync(0xffffffffu, lsum0, 2);
    lsum1 += __shfl_xor_sync(0xffffffffu, lsum1, 1);
    lsum1 += __shfl_xor_sync(0xffffffffu, lsum1, 2);
    float inv0 = 1.0f / lsum0;
    float inv1 = 1.0f / lsum1;

    float* xA = g_x + ((size_t)(b * LQ + rowA)) * DIM + h * HD;
    float* xB = xA + (size_t)8 * DIM;
#pragma unroll
    for (int nd = 0; nd < 6; nd++) {
        int c = nd * 8 + (lane & 3) * 2;
        *(float2*)(xA + c) = make_float2(oacc[nd][0] * inv0, oacc[nd][1] * inv0);
        *(float2*)(xB + c) = make_float2(oacc[nd][2] * inv1, oacc[nd][3] * inv1);
    }
}

// ---------------------------------------------------------------------------
extern "C" void kernel_launch(void* const* d_in, const int* in_sizes, int n_in,
                              void* d_out, int out_size)
{
    const float* tem_mask    = (const float*)d_in[0];
    const float* search_mask = (const float*)d_in[1];
    const float* q           = (const float*)d_in[2];
    const float* kv          = (const float*)d_in[3];
    const float* attn_pos    = (const float*)d_in[4];
    const float* q_w         = (const float*)d_in[5];
    const float* q_b         = (const float*)d_in[6];
    const float* kv_w        = (const float*)d_in[7];
    const float* kv_b        = (const float*)d_in[8];
    const float* proj_w      = (const float*)d_in[9];
    const float* proj_b      = (const float*)d_in[10];
    float* out = (float*)d_out;

    sgemm_kernel<0><<<dim3(3, 128), 256>>>(q, q_w, q_b, nullptr, nullptr, nullptr);
    sgemm_kernel<1><<<dim3(6, 178), 256>>>(kv, kv_w, kv_b, tem_mask, search_mask, nullptr);
    attn_kernel<<<B * H * (LQ / 64), 128>>>(attn_pos);
    sgemm_kernel<2><<<dim3(3, 128), 256>>>(nullptr, proj_w, proj_b, nullptr, nullptr, out);
}

// round 9
// speedup vs baseline: 2.1370x; 1.3918x over previous
#include <cuda_runtime.h>
#include <cuda_bf16.h>
#include <stdint.h>

// ---------------------------------------------------------------------------
// B=16, Lq=1024, Lkv=1424, DIM=384, HEADS=8, HEAD_DIM=48, TEM_LEN=400
// projections: mma.sync bf16 hi/lo GEMM (3-product split, fp32-grade)
// attention:   mma.sync bf16 hi/lo flash kernel, fixed-max softmax
// ---------------------------------------------------------------------------

constexpr int B    = 16;
constexpr int H    = 8;
constexpr int DIM  = 384;
constexpr int HD   = 48;
constexpr int LQ   = 1024;
constexpr int LKV  = 1424;
constexpr int TEM  = 400;
constexpr float ATTN_SCALE = 0.14433756729740643f;  // 48^-0.5
constexpr float M_FIX = 12.0f;

using u64 = unsigned long long;
using u32 = unsigned int;

// ---- scratch ---------------------------------------------------------------
__device__ __nv_bfloat16 g_qhi[B * H * LQ * HD];    // (b,h,q,d) pre-scaled
__device__ __nv_bfloat16 g_qlo[B * H * LQ * HD];
__device__ __nv_bfloat16 g_khi[B * H * LKV * HD];   // (b,h,s,d)
__device__ __nv_bfloat16 g_klo[B * H * LKV * HD];
__device__ __nv_bfloat16 g_vthi[B * H * HD * LKV];  // (b,h,d,s) transposed
__device__ __nv_bfloat16 g_vtlo[B * H * HD * LKV];
__device__ float g_x[B * LQ * DIM];

// ---- mma.sync / ldmatrix wrappers ------------------------------------------
__device__ __forceinline__ u32 smu32(const void* p) {
    u32 a;
    asm("{ .reg .u64 t; cvta.to.shared.u64 t, %1; cvt.u32.u64 %0, t; }"
        : "=r"(a) : "l"(p));
    return a;
}
__device__ __forceinline__ void ldmx4(u32* r, u32 addr) {
    asm volatile("ldmatrix.sync.aligned.m8n8.x4.shared.b16 {%0,%1,%2,%3}, [%4];"
                 : "=r"(r[0]), "=r"(r[1]), "=r"(r[2]), "=r"(r[3]) : "r"(addr));
}
__device__ __forceinline__ void ldmx2(u32* r, u32 addr) {
    asm volatile("ldmatrix.sync.aligned.m8n8.x2.shared.b16 {%0,%1}, [%2];"
                 : "=r"(r[0]), "=r"(r[1]) : "r"(addr));
}
__device__ __forceinline__ void mma16816(float* d, const u32* a, const u32* b) {
    asm volatile(
        "mma.sync.aligned.m16n8k16.row.col.f32.bf16.bf16.f32 "
        "{%0,%1,%2,%3}, {%4,%5,%6,%7}, {%8,%9}, {%0,%1,%2,%3};"
        : "+f"(d[0]), "+f"(d[1]), "+f"(d[2]), "+f"(d[3])
        : "r"(a[0]), "r"(a[1]), "r"(a[2]), "r"(a[3]), "r"(b[0]), "r"(b[1]));
}
// pack (lo, hi) floats -> bf16x2 register (lo -> lower 16 bits)
__device__ __forceinline__ u32 cvt2bf(float lo, float hi) {
    u32 d; asm("cvt.rn.bf16x2.f32 %0, %1, %2;" : "=r"(d) : "f"(hi), "f"(lo));
    return d;
}
__device__ __forceinline__ u32 packbf(__nv_bfloat16 lo, __nv_bfloat16 hi) {
    return ((u32)__bfloat16_as_ushort(hi) << 16) | (u32)__bfloat16_as_ushort(lo);
}

// ---------------------------------------------------------------------------
// Tensor-core GEMM: out[m][n] = sum_k A[m][k] * W[n][k] + bias[n], K=384.
// Block 128x128, 256 threads (8 warps: 4m x 2n), warp = 32x64.
// A and W split hi/lo bf16 at smem fill; 3 mma products per tile.
// MODE 0: q-proj -> g_qhi/lo (pre-scaled)
// MODE 1: kv-proj -> g_khi/lo + g_vthi/lo (+masks, transposed)
// MODE 2: out-proj (fp32, reads g_x)
// ---------------------------------------------------------------------------
constexpr int GST = 40;   // bf16 row stride (80B): (5r mod 8) -> conflict-free

template <int MODE>
__device__ __forceinline__ void scatter_elem(
    int m, int n, float v,
    const float* __restrict__ bias,
    const float* __restrict__ tmask, const float* __restrict__ smask,
    float* __restrict__ out)
{
    v += bias[n];
    if (MODE == 0) {
        int b  = m >> 10;
        int qi = m & 1023;
        int h  = n / HD;
        int d  = n - h * HD;
        float vs = v * ATTN_SCALE;
        __nv_bfloat16 hb = __float2bfloat16(vs);
        float lo = vs - __bfloat162float(hb);
        size_t o = ((size_t)(b * H + h) * LQ + qi) * HD + d;
        g_qhi[o] = hb;
        g_qlo[o] = __float2bfloat16(lo);
    } else if (MODE == 1) {
        int b = m / LKV;
        int s = m - b * LKV;
        if (n < DIM) {
            int h = n / HD, d = n - h * HD;
            __nv_bfloat16 hb = __float2bfloat16(v);
            float lo = v - __bfloat162float(hb);
            size_t o = ((size_t)(b * H + h) * LKV + s) * HD + d;
            g_khi[o] = hb;
            g_klo[o] = __float2bfloat16(lo);
        } else {
            int nv = n - DIM;
            float mv = (s < TEM)
                ? tmask[((size_t)(b * TEM + s)) * DIM + nv]
                : smask[((size_t)(b * (LKV - TEM) + (s - TEM))) * DIM + nv];
            v += mv;
            int h = nv / HD, d = nv - h * HD;
            __nv_bfloat16 hb = __float2bfloat16(v);
            float lo = v - __bfloat162float(hb);
            size_t o = ((size_t)(b * H + h) * HD + d) * LKV + s;
            g_vthi[o] = hb;
            g_vtlo[o] = __float2bfloat16(lo);
        }
    } else {
        out[(size_t)m * DIM + n] = v;
    }
}

template <int MODE>
__global__ __launch_bounds__(256) void mgemm_kernel(
    const float* __restrict__ A, const float* __restrict__ W,
    const float* __restrict__ bias,
    const float* __restrict__ tmask, const float* __restrict__ smask,
    float* __restrict__ out)
{
    __shared__ __align__(16) __nv_bfloat16 Ah[128][GST];
    __shared__ __align__(16) __nv_bfloat16 Al[128][GST];
    __shared__ __align__(16) __nv_bfloat16 Bh[128][GST];
    __shared__ __align__(16) __nv_bfloat16 Bl[128][GST];

    const int m0   = blockIdx.y * 128;
    const int n0   = blockIdx.x * 128;
    const int tid  = threadIdx.x;
    const int warp = tid >> 5;
    const int lane = tid & 31;
    const int l16  = lane & 15;
    const int wm   = warp & 3;      // 4 m-strips of 32
    const int wn   = warp >> 2;     // 2 n-strips of 64

    const u32 sAh = smu32(&Ah[0][0]), sAl = smu32(&Al[0][0]);
    const u32 sBh = smu32(&Bh[0][0]), sBl = smu32(&Bl[0][0]);

    float acc[2][8][4];
#pragma unroll
    for (int mi = 0; mi < 2; mi++)
#pragma unroll
        for (int nj = 0; nj < 8; nj++)
#pragma unroll
            for (int j = 0; j < 4; j++) acc[mi][nj][j] = 0.0f;

    const float* Aptr = (MODE == 2) ? (&g_x[0] + (size_t)m0 * DIM)
                                    : (A + (size_t)m0 * DIM);
    const float* Wptr = W + (size_t)n0 * DIM;

    const int lrow = tid >> 1;            // 0..127
    const int lkc  = (tid & 1) * 16;      // 0 or 16

    for (int k0 = 0; k0 < DIM; k0 += 32) {
        __syncthreads();   // previous buffer's reads complete
#pragma unroll
        for (int j = 0; j < 4; j++) {
            float4 a = *(const float4*)(Aptr + (size_t)lrow * DIM + k0 + lkc + j * 4);
            __nv_bfloat16 h0 = __float2bfloat16(a.x), h1 = __float2bfloat16(a.y);
            __nv_bfloat16 h2 = __float2bfloat16(a.z), h3 = __float2bfloat16(a.w);
            *(uint2*)&Ah[lrow][lkc + j * 4] = make_uint2(packbf(h0, h1), packbf(h2, h3));
            *(uint2*)&Al[lrow][lkc + j * 4] = make_uint2(
                cvt2bf(a.x - __bfloat162float(h0), a.y - __bfloat162float(h1)),
                cvt2bf(a.z - __bfloat162float(h2), a.w - __bfloat162float(h3)));
            float4 b = *(const float4*)(Wptr + (size_t)lrow * DIM + k0 + lkc + j * 4);
            __nv_bfloat16 g0 = __float2bfloat16(b.x), g1 = __float2bfloat16(b.y);
            __nv_bfloat16 g2 = __float2bfloat16(b.z), g3 = __float2bfloat16(b.w);
            *(uint2*)&Bh[lrow][lkc + j * 4] = make_uint2(packbf(g0, g1), packbf(g2, g3));
            *(uint2*)&Bl[lrow][lkc + j * 4] = make_uint2(
                cvt2bf(b.x - __bfloat162float(g0), b.y - __bfloat162float(g1)),
                cvt2bf(b.z - __bfloat162float(g2), b.w - __bfloat162float(g3)));
        }
        __syncthreads();

#pragma unroll
        for (int ks = 0; ks < 2; ks++) {
            u32 ahf[2][4], alf[2][4];
#pragma unroll
            for (int mi = 0; mi < 2; mi++) {
                u32 aoff = (u32)((wm * 32 + mi * 16 + l16) * (GST * 2)
                                 + (lane >> 4) * 16 + ks * 32);
                ldmx4(ahf[mi], sAh + aoff);
                ldmx4(alf[mi], sAl + aoff);
            }
#pragma unroll
            for (int nj = 0; nj < 8; nj++) {
                u32 boff = (u32)((wn * 64 + nj * 8 + (l16 & 7)) * (GST * 2)
                                 + (l16 >> 3) * 16 + ks * 32);
                u32 bhf[2], blf[2];
                ldmx2(bhf, sBh + boff);
                ldmx2(blf, sBl + boff);
#pragma unroll
                for (int mi = 0; mi < 2; mi++) {
                    mma16816(acc[mi][nj], ahf[mi], bhf);
                    mma16816(acc[mi][nj], alf[mi], bhf);
                    mma16816(acc[mi][nj], ahf[mi], blf);
                }
            }
        }
    }

    // ---- epilogue: scatter accumulators ----
#pragma unroll
    for (int mi = 0; mi < 2; mi++) {
#pragma unroll
        for (int rh = 0; rh < 2; rh++) {
            int m = m0 + wm * 32 + mi * 16 + rh * 8 + (lane >> 2);
#pragma unroll
            for (int nj = 0; nj < 8; nj++) {
                int n = n0 + wn * 64 + nj * 8 + (lane & 3) * 2;
                scatter_elem<MODE>(m, n,     acc[mi][nj][rh * 2 + 0], bias, tmask, smask, out);
                scatter_elem<MODE>(m, n + 1, acc[mi][nj][rh * 2 + 1], bias, tmask, smask, out);
            }
        }
    }
}

// ---------------------------------------------------------------------------
// mma.sync flash attention.  Block = (b, h, 64-q tile), 128 threads (4 warps),
// each warp owns 16 q rows.  kv tiles of 64.  (unchanged from R7 winner)
// ---------------------------------------------------------------------------
constexpr int QK_STRIDE = 56;   // 112B rows -> conflict-free ldmatrix
constexpr int V_STRIDE  = 72;   // 144B rows

__global__ __launch_bounds__(128) void attn_kernel(const float* __restrict__ pos)
{
    __shared__ __align__(16) __nv_bfloat16 Qh[64][QK_STRIDE];
    __shared__ __align__(16) __nv_bfloat16 Ql[64][QK_STRIDE];
    __shared__ __align__(16) __nv_bfloat16 Kh[64][QK_STRIDE];
    __shared__ __align__(16) __nv_bfloat16 Kl[64][QK_STRIDE];
    __shared__ __align__(16) __nv_bfloat16 Vh[48][V_STRIDE];
    __shared__ __align__(16) __nv_bfloat16 Vl[48][V_STRIDE];

    const int tid   = threadIdx.x;
    const int warp  = tid >> 5;
    const int lane  = tid & 31;
    const int l16   = lane & 15;
    const int bid   = blockIdx.x;
    const int b     = bid & 15;            // batch fastest: pos L2 reuse x16
    const int qt    = (bid >> 4) & 15;
    const int h     = bid >> 8;
    const int q0    = qt * 64;
    const int bh    = b * H + h;
    const int qrow0 = warp * 16;

    const u32 sQh = smu32(&Qh[0][0]), sQl = smu32(&Ql[0][0]);
    const u32 sKh = smu32(&Kh[0][0]), sKl = smu32(&Kl[0][0]);
    const u32 sVh = smu32(&Vh[0][0]), sVl = smu32(&Vl[0][0]);

    {
        const __nv_bfloat16* qh = g_qhi + ((size_t)bh * LQ + q0) * HD;
        const __nv_bfloat16* ql = g_qlo + ((size_t)bh * LQ + q0) * HD;
#pragma unroll
        for (int l = 0; l < 3; l++) {
            int idx = tid + 128 * l;
            int row = idx / 6, c = idx % 6;
            *(uint4*)&Qh[row][c * 8] = *(const uint4*)(qh + row * HD + c * 8);
            *(uint4*)&Ql[row][c * 8] = *(const uint4*)(ql + row * HD + c * 8);
        }
    }
    __syncthreads();

    u32 qfh[3][4], qfl[3][4];
    {
        u32 qoff = (u32)((qrow0 + l16) * (QK_STRIDE * 2) + (lane >> 4) * 16);
#pragma unroll
        for (int ks = 0; ks < 3; ks++) {
            ldmx4(qfh[ks], sQh + qoff + ks * 32);
            ldmx4(qfl[ks], sQl + qoff + ks * 32);
        }
    }

    const __nv_bfloat16* kh = g_khi + (size_t)bh * LKV * HD;
    const __nv_bfloat16* kl = g_klo + (size_t)bh * LKV * HD;
    const __nv_bfloat16* vh = g_vthi + (size_t)bh * HD * LKV;
    const __nv_bfloat16* vl = g_vtlo + (size_t)bh * HD * LKV;

    const int rowA = q0 + qrow0 + (lane >> 2);
    const float* posA = pos + ((size_t)h * LQ + rowA) * LKV;
    const float* posB = posA + (size_t)8 * LKV;

    float oacc[6][4];
#pragma unroll
    for (int n = 0; n < 6; n++)
#pragma unroll
        for (int j = 0; j < 4; j++) oacc[n][j] = 0.0f;
    float lsum0 = 0.0f, lsum1 = 0.0f;

    constexpr int NT = (LKV + 63) / 64;  // 23

    for (int t = 0; t < NT; t++) {
        const int kv0 = t * 64;

        __syncthreads();

#pragma unroll
        for (int l = 0; l < 3; l++) {
            int idx = tid + 128 * l;
            int row = idx / 6, c = idx % 6;
            int srow = kv0 + row; if (srow >= LKV) srow = LKV - 1;
            *(uint4*)&Kh[row][c * 8] = *(const uint4*)(kh + (size_t)srow * HD + c * 8);
            *(uint4*)&Kl[row][c * 8] = *(const uint4*)(kl + (size_t)srow * HD + c * 8);
        }
#pragma unroll
        for (int l = 0; l < 3; l++) {
            int idx = tid + 128 * l;
            int row = idx / 8, c = idx % 8;
            int skv = kv0 + c * 8; if (skv + 8 > LKV) skv = LKV - 8;
            *(uint4*)&Vh[row][c * 8] = *(const uint4*)(vh + (size_t)row * LKV + skv);
            *(uint4*)&Vl[row][c * 8] = *(const uint4*)(vl + (size_t)row * LKV + skv);
        }
        __syncthreads();

        float sacc[8][4];
#pragma unroll
        for (int n = 0; n < 8; n++)
#pragma unroll
            for (int j = 0; j < 4; j++) sacc[n][j] = 0.0f;

#pragma unroll
        for (int nn = 0; nn < 8; nn++) {
            u32 koff = (u32)((nn * 8 + (l16 & 7)) * (QK_STRIDE * 2) + (l16 >> 3) * 16);
#pragma unroll
            for (int ks = 0; ks < 3; ks++) {
                u32 bh2[2], bl2[2];
                ldmx2(bh2, sKh + koff + ks * 32);
                ldmx2(bl2, sKl + koff + ks * 32);
                mma16816(sacc[nn], qfh[ks], bh2);
                mma16816(sacc[nn], qfl[ks], bh2);
                mma16816(sacc[nn], qfh[ks], bl2);
            }
        }

#pragma unroll
        for (int nn = 0; nn < 8; nn++) {
            int col = kv0 + nn * 8 + (lane & 3) * 2;
            if (col < LKV) {
                float2 pA = *(const float2*)(posA + col);
                float2 pB = *(const float2*)(posB + col);
                float p0 = __expf(sacc[nn][0] + pA.x - M_FIX);
                float p1 = __expf(sacc[nn][1] + pA.y - M_FIX);
                float p2 = __expf(sacc[nn][2] + pB.x - M_FIX);
                float p3 = __expf(sacc[nn][3] + pB.y - M_FIX);
                sacc[nn][0] = p0; sacc[nn][1] = p1;
                sacc[nn][2] = p2; sacc[nn][3] = p3;
                lsum0 += p0 + p1;
                lsum1 += p2 + p3;
            } else {
                sacc[nn][0] = 0.f; sacc[nn][1] = 0.f;
                sacc[nn][2] = 0.f; sacc[nn][3] = 0.f;
            }
        }

#pragma unroll
        for (int kk = 0; kk < 4; kk++) {
            u32 pah[4], pal[4];
#pragma unroll
            for (int half = 0; half < 2; half++) {
                int cn = 2 * kk + half;
                float p0 = sacc[cn][0], p1 = sacc[cn][1];
                float p2 = sacc[cn][2], p3 = sacc[cn][3];
                float h0 = __bfloat162float(__float2bfloat16(p0));
                float h1 = __bfloat162float(__float2bfloat16(p1));
                float h2 = __bfloat162float(__float2bfloat16(p2));
                float h3 = __bfloat162float(__float2bfloat16(p3));
                if (half == 0) {
                    pah[0] = cvt2bf(p0, p1);
                    pah[1] = cvt2bf(p2, p3);
                    pal[0] = cvt2bf(p0 - h0, p1 - h1);
                    pal[1] = cvt2bf(p2 - h2, p3 - h3);
                } else {
                    pah[2] = cvt2bf(p0, p1);
                    pah[3] = cvt2bf(p2, p3);
                    pal[2] = cvt2bf(p0 - h0, p1 - h1);
                    pal[3] = cvt2bf(p2 - h2, p3 - h3);
                }
            }
#pragma unroll
            for (int nd = 0; nd < 6; nd++) {
                u32 voff = (u32)((nd * 8 + (l16 & 7)) * (V_STRIDE * 2) + kk * 32 + (l16 >> 3) * 16);
                u32 vfh[2], vfl[2];
                ldmx2(vfh, sVh + voff);
                ldmx2(vfl, sVl + voff);
                mma16816(oacc[nd], pah, vfh);
                mma16816(oacc[nd], pal, vfh);
                mma16816(oacc[nd], pah, vfl);
            }
        }
    }

    lsum0 += __shfl_xor_sync(0xffffffffu, lsum0, 1);
    lsum0 += __shfl_xor_sync(0xffffffffu, lsum0, 2);
    lsum1 += __shfl_xor_sync(0xffffffffu, lsum1, 1);
    lsum1 += __shfl_xor_sync(0xffffffffu, lsum1, 2);
    float inv0 = 1.0f / lsum0;
    float inv1 = 1.0f / lsum1;

    float* xA = g_x + ((size_t)(b * LQ + rowA)) * DIM + h * HD;
    float* xB = xA + (size_t)8 * DIM;
#pragma unroll
    for (int nd = 0; nd < 6; nd++) {
        int c = nd * 8 + (lane & 3) * 2;
        *(float2*)(xA + c) = make_float2(oacc[nd][0] * inv0, oacc[nd][1] * inv0);
        *(float2*)(xB + c) = make_float2(oacc[nd][2] * inv1, oacc[nd][3] * inv1);
    }
}

// ---------------------------------------------------------------------------
extern "C" void kernel_launch(void* const* d_in, const int* in_sizes, int n_in,
                              void* d_out, int out_size)
{
    const float* tem_mask    = (const float*)d_in[0];
    const float* search_mask = (const float*)d_in[1];
    const float* q           = (const float*)d_in[2];
    const float* kv          = (const float*)d_in[3];
    const float* attn_pos    = (const float*)d_in[4];
    const float* q_w         = (const float*)d_in[5];
    const float* q_b         = (const float*)d_in[6];
    const float* kv_w        = (const float*)d_in[7];
    const float* kv_b        = (const float*)d_in[8];
    const float* proj_w      = (const float*)d_in[9];
    const float* proj_b      = (const float*)d_in[10];
    float* out = (float*)d_out;

    mgemm_kernel<0><<<dim3(3, 128), 256>>>(q, q_w, q_b, nullptr, nullptr, nullptr);
    mgemm_kernel<1><<<dim3(6, 178), 256>>>(kv, kv_w, kv_b, tem_mask, search_mask, nullptr);
    attn_kernel<<<B * H * (LQ / 64), 128>>>(attn_pos);
    mgemm_kernel<2><<<dim3(3, 128), 256>>>(nullptr, proj_w, proj_b, nullptr, nullptr, out);
}